// round 4
// baseline (speedup 1.0000x reference)
#include <cuda_runtime.h>

// Quintic Hermite spline evaluation, coefficient-table + software-pipelined.
// Inputs: x_new [N] f32, knots [nk] f32, function_values [3*nk] f32.
// Output: [N] f32.

__device__ __forceinline__ float eval_one(
    float xq, float k0, float scale, int nkm2,
    const float4* __restrict__ cA, const float4* __restrict__ cB)
{
    int g = (int)((xq - k0) * scale);
    g = max(0, min(g, nkm2));
    float4 a = cA[g];   // {c5, c4, c3, c2 = h2*ddyl}
    float4 b = cB[g];   // {c1 = h*dyl, c0 = yl, xl, inv_h}
    float t = (xq - b.z) * b.w;
    float v = a.x;
    v = v * t + a.y;
    v = v * t + a.z;
    v = v * t + a.w;
    v = v * t + b.x;
    v = v * t + b.y;
    return v;
}

__global__ void __launch_bounds__(256, 7) quintic_spline_kernel(
    const float* __restrict__ x,
    const float* __restrict__ knots,
    const float* __restrict__ fv,
    float* __restrict__ out,
    int n, int nk)
{
    extern __shared__ float4 smem4[];
    float4* cA = smem4;        // nk entries (nk-1 used)
    float4* cB = cA + nk;      // nk entries

    // build per-interval coefficient table (4 trips/thread at nk=1024)
    for (int i = threadIdx.x; i < nk - 1; i += blockDim.x) {
        float xl = knots[i];
        float h  = knots[i + 1] - xl;
        float yl   = fv[i],          yr   = fv[i + 1];
        float dyl  = fv[nk + i],     dyr  = fv[nk + i + 1];
        float ddyl = fv[2 * nk + i], ddyr = fv[2 * nk + i + 1];

        float dY = yr - yl;
        float h2 = 0.5f * h * h;
        float c5 =   6.0f * dY - 3.0f * h * (dyl + dyr)               + h2 * (ddyr - ddyl);
        float c4 = -15.0f * dY + h * (8.0f * dyl + 7.0f * dyr)        - h2 * (2.0f * ddyr - 3.0f * ddyl);
        float c3 =  10.0f * dY - 2.0f * h * (3.0f * dyl + 2.0f * dyr) + h2 * (ddyr - 3.0f * ddyl);

        cA[i] = make_float4(c5, c4, c3, h2 * ddyl);
        cB[i] = make_float4(h * dyl, yl, xl, 1.0f / h);
    }
    __syncthreads();

    const float k0 = knots[0];
    const float scale = (float)(nk - 1) / (knots[nk - 1] - k0);
    const int nkm2 = nk - 2;

    const int n4 = n >> 2;
    const int stride = gridDim.x * blockDim.x;
    int i4 = blockIdx.x * blockDim.x + threadIdx.x;

    if (i4 < n4) {
        // software pipeline: prefetch next x chunk while evaluating current
        float4 xcur = reinterpret_cast<const float4*>(x)[i4];
        while (true) {
            int inext = i4 + stride;
            float4 xnext;
            bool have_next = (inext < n4);
            if (have_next)
                xnext = reinterpret_cast<const float4*>(x)[inext];

            float4 r;
            r.x = eval_one(xcur.x, k0, scale, nkm2, cA, cB);
            r.y = eval_one(xcur.y, k0, scale, nkm2, cA, cB);
            r.z = eval_one(xcur.z, k0, scale, nkm2, cA, cB);
            r.w = eval_one(xcur.w, k0, scale, nkm2, cA, cB);
            reinterpret_cast<float4*>(out)[i4] = r;

            if (!have_next) break;
            xcur = xnext;
            i4 = inext;
        }
    }

    // tail (n not divisible by 4)
    int tail = n & 3;
    int base = n4 << 2;
    int gid = blockIdx.x * blockDim.x + threadIdx.x;
    if (gid < tail) {
        float xq = x[base + gid];
        out[base + gid] = eval_one(xq, k0, scale, nkm2, cA, cB);
    }
}

extern "C" void kernel_launch(void* const* d_in, const int* in_sizes, int n_in,
                              void* d_out, int out_size)
{
    const float* x     = (const float*)d_in[0];
    const float* knots = (const float*)d_in[1];
    const float* fv    = (const float*)d_in[2];
    float* out = (float*)d_out;

    int n  = in_sizes[0];
    int nk = in_sizes[1];

    // ask for max shared-memory carveout so 7 blocks/SM (224KB) fit
    cudaFuncSetAttribute(quintic_spline_kernel,
                         cudaFuncAttributePreferredSharedMemoryCarveout, 100);

    const int threads = 256;
    int n4 = (n + 3) >> 2;
    int blocks = (n4 + threads - 1) / threads;
    int cap = 148 * 7;  // one full resident wave at 7 blocks/SM
    if (blocks > cap) blocks = cap;
    if (blocks < 1) blocks = 1;

    size_t smem_bytes = (size_t)2 * nk * sizeof(float4);
    quintic_spline_kernel<<<blocks, threads, smem_bytes>>>(x, knots, fv, out, n, nk);
}

// round 5
// speedup vs baseline: 1.1391x; 1.1391x over previous
#include <cuda_runtime.h>

// Quintic Hermite spline evaluation, coefficient-table version.
// Inputs: x_new [N] f32, knots [nk] f32, function_values [3*nk] f32.
// Output: [N] f32.
//
// 512-thread blocks: the 32KB per-block coefficient table is amortized over
// twice as many threads, letting 4 blocks/SM hit the 2048-thread cap (100%
// theoretical occupancy) within 132KB smem/SM.

__device__ __forceinline__ float eval_one(
    float xq, float k0, float scale, int nkm2,
    const float4* __restrict__ cA, const float4* __restrict__ cB)
{
    int g = (int)((xq - k0) * scale);
    g = max(0, min(g, nkm2));
    float4 a = cA[g];   // {c5, c4, c3, c2 = h2*ddyl}
    float4 b = cB[g];   // {c1 = h*dyl, c0 = yl, xl, inv_h}
    float t = (xq - b.z) * b.w;
    float v = a.x;
    v = v * t + a.y;
    v = v * t + a.z;
    v = v * t + a.w;
    v = v * t + b.x;
    v = v * t + b.y;
    return v;
}

__global__ void __launch_bounds__(512, 4) quintic_spline_kernel(
    const float* __restrict__ x,
    const float* __restrict__ knots,
    const float* __restrict__ fv,
    float* __restrict__ out,
    int n, int nk)
{
    extern __shared__ float4 smem4[];
    float4* cA = smem4;        // nk entries (nk-1 used)
    float4* cB = cA + nk;      // nk entries

    // build per-interval coefficient table (2 trips/thread at nk=1024)
    for (int i = threadIdx.x; i < nk - 1; i += blockDim.x) {
        float xl = knots[i];
        float h  = knots[i + 1] - xl;
        float yl   = fv[i],          yr   = fv[i + 1];
        float dyl  = fv[nk + i],     dyr  = fv[nk + i + 1];
        float ddyl = fv[2 * nk + i], ddyr = fv[2 * nk + i + 1];

        float dY = yr - yl;
        float h2 = 0.5f * h * h;
        float c5 =   6.0f * dY - 3.0f * h * (dyl + dyr)               + h2 * (ddyr - ddyl);
        float c4 = -15.0f * dY + h * (8.0f * dyl + 7.0f * dyr)        - h2 * (2.0f * ddyr - 3.0f * ddyl);
        float c3 =  10.0f * dY - 2.0f * h * (3.0f * dyl + 2.0f * dyr) + h2 * (ddyr - 3.0f * ddyl);

        cA[i] = make_float4(c5, c4, c3, h2 * ddyl);
        cB[i] = make_float4(h * dyl, yl, xl, 1.0f / h);
    }
    __syncthreads();

    const float k0 = knots[0];
    const float scale = (float)(nk - 1) / (knots[nk - 1] - k0);
    const int nkm2 = nk - 2;

    const int n4 = n >> 2;
    const int stride = gridDim.x * blockDim.x;
    int i4 = blockIdx.x * blockDim.x + threadIdx.x;

    if (i4 < n4) {
        // software pipeline: prefetch next x chunk while evaluating current
        float4 xcur = reinterpret_cast<const float4*>(x)[i4];
        while (true) {
            int inext = i4 + stride;
            float4 xnext;
            bool have_next = (inext < n4);
            if (have_next)
                xnext = reinterpret_cast<const float4*>(x)[inext];

            float4 r;
            r.x = eval_one(xcur.x, k0, scale, nkm2, cA, cB);
            r.y = eval_one(xcur.y, k0, scale, nkm2, cA, cB);
            r.z = eval_one(xcur.z, k0, scale, nkm2, cA, cB);
            r.w = eval_one(xcur.w, k0, scale, nkm2, cA, cB);
            reinterpret_cast<float4*>(out)[i4] = r;

            if (!have_next) break;
            xcur = xnext;
            i4 = inext;
        }
    }

    // tail (n not divisible by 4)
    int tail = n & 3;
    int base = n4 << 2;
    int gid = blockIdx.x * blockDim.x + threadIdx.x;
    if (gid < tail) {
        float xq = x[base + gid];
        out[base + gid] = eval_one(xq, k0, scale, nkm2, cA, cB);
    }
}

extern "C" void kernel_launch(void* const* d_in, const int* in_sizes, int n_in,
                              void* d_out, int out_size)
{
    const float* x     = (const float*)d_in[0];
    const float* knots = (const float*)d_in[1];
    const float* fv    = (const float*)d_in[2];
    float* out = (float*)d_out;

    int n  = in_sizes[0];
    int nk = in_sizes[1];

    cudaFuncSetAttribute(quintic_spline_kernel,
                         cudaFuncAttributePreferredSharedMemoryCarveout, 100);

    const int threads = 512;
    int n4 = (n + 3) >> 2;
    int blocks = (n4 + threads - 1) / threads;
    int cap = 148 * 4;  // one full resident wave at 4 blocks/SM (2048 thr/SM)
    if (blocks > cap) blocks = cap;
    if (blocks < 1) blocks = 1;

    size_t smem_bytes = (size_t)2 * nk * sizeof(float4);
    quintic_spline_kernel<<<blocks, threads, smem_bytes>>>(x, knots, fv, out, n, nk);
}

// round 6
// speedup vs baseline: 1.1737x; 1.0303x over previous
#include <cuda_runtime.h>

// Quintic Hermite spline evaluation, coefficient-table version.
// Inputs: x_new [N] f32, knots [nk] f32, function_values [3*nk] f32.
// Output: [N] f32.
//
// 384-thread blocks, 42-reg budget: pairs of queries are evaluated with all
// four LDS.128 coefficient gathers issued before either Horner chain, keeping
// >=4 shared-memory loads in flight per warp to hide LDS latency.

__global__ void __launch_bounds__(384, 4) quintic_spline_kernel(
    const float* __restrict__ x,
    const float* __restrict__ knots,
    const float* __restrict__ fv,
    float* __restrict__ out,
    int n, int nk)
{
    extern __shared__ float4 smem4[];
    float4* cA = smem4;        // nk entries (nk-1 used): {c5, c4, c3, c2}
    float4* cB = cA + nk;      // nk entries:             {c1, c0, xl, inv_h}

    // build per-interval coefficient table
    for (int i = threadIdx.x; i < nk - 1; i += blockDim.x) {
        float xl = knots[i];
        float h  = knots[i + 1] - xl;
        float yl   = fv[i],          yr   = fv[i + 1];
        float dyl  = fv[nk + i],     dyr  = fv[nk + i + 1];
        float ddyl = fv[2 * nk + i], ddyr = fv[2 * nk + i + 1];

        float dY = yr - yl;
        float h2 = 0.5f * h * h;
        float c5 =   6.0f * dY - 3.0f * h * (dyl + dyr)               + h2 * (ddyr - ddyl);
        float c4 = -15.0f * dY + h * (8.0f * dyl + 7.0f * dyr)        - h2 * (2.0f * ddyr - 3.0f * ddyl);
        float c3 =  10.0f * dY - 2.0f * h * (3.0f * dyl + 2.0f * dyr) + h2 * (ddyr - 3.0f * ddyl);

        cA[i] = make_float4(c5, c4, c3, h2 * ddyl);
        cB[i] = make_float4(h * dyl, yl, xl, 1.0f / h);
    }
    __syncthreads();

    const float k0 = knots[0];
    const float scale = (float)(nk - 1) / (knots[nk - 1] - k0);
    const int nkm2 = nk - 2;

    const int n4 = n >> 2;
    const int stride = gridDim.x * blockDim.x;
    int i4 = blockIdx.x * blockDim.x + threadIdx.x;

    if (i4 < n4) {
        float4 xcur = reinterpret_cast<const float4*>(x)[i4];
        while (true) {
            int inext = i4 + stride;
            float4 xnext;
            bool have_next = (inext < n4);
            if (have_next)
                xnext = reinterpret_cast<const float4*>(x)[inext];

            float4 r;
            // ---- pair 0: elements x, y ----
            {
                int g0 = (int)((xcur.x - k0) * scale);
                int g1 = (int)((xcur.y - k0) * scale);
                g0 = max(0, min(g0, nkm2));
                g1 = max(0, min(g1, nkm2));
                float4 a0 = cA[g0];
                float4 b0 = cB[g0];
                float4 a1 = cA[g1];
                float4 b1 = cB[g1];
                float t0 = (xcur.x - b0.z) * b0.w;
                float t1 = (xcur.y - b1.z) * b1.w;
                float v0 = a0.x, v1 = a1.x;
                v0 = v0 * t0 + a0.y;  v1 = v1 * t1 + a1.y;
                v0 = v0 * t0 + a0.z;  v1 = v1 * t1 + a1.z;
                v0 = v0 * t0 + a0.w;  v1 = v1 * t1 + a1.w;
                v0 = v0 * t0 + b0.x;  v1 = v1 * t1 + b1.x;
                v0 = v0 * t0 + b0.y;  v1 = v1 * t1 + b1.y;
                r.x = v0; r.y = v1;
            }
            // ---- pair 1: elements z, w ----
            {
                int g0 = (int)((xcur.z - k0) * scale);
                int g1 = (int)((xcur.w - k0) * scale);
                g0 = max(0, min(g0, nkm2));
                g1 = max(0, min(g1, nkm2));
                float4 a0 = cA[g0];
                float4 b0 = cB[g0];
                float4 a1 = cA[g1];
                float4 b1 = cB[g1];
                float t0 = (xcur.z - b0.z) * b0.w;
                float t1 = (xcur.w - b1.z) * b1.w;
                float v0 = a0.x, v1 = a1.x;
                v0 = v0 * t0 + a0.y;  v1 = v1 * t1 + a1.y;
                v0 = v0 * t0 + a0.z;  v1 = v1 * t1 + a1.z;
                v0 = v0 * t0 + a0.w;  v1 = v1 * t1 + a1.w;
                v0 = v0 * t0 + b0.x;  v1 = v1 * t1 + b1.x;
                v0 = v0 * t0 + b0.y;  v1 = v1 * t1 + b1.y;
                r.z = v0; r.w = v1;
            }
            reinterpret_cast<float4*>(out)[i4] = r;

            if (!have_next) break;
            xcur = xnext;
            i4 = inext;
        }
    }

    // tail (n not divisible by 4)
    int tail = n & 3;
    int base = n4 << 2;
    int gid = blockIdx.x * blockDim.x + threadIdx.x;
    if (gid < tail) {
        float xq = x[base + gid];
        int g = (int)((xq - k0) * scale);
        g = max(0, min(g, nkm2));
        float4 a = cA[g];
        float4 b = cB[g];
        float t = (xq - b.z) * b.w;
        float v = a.x;
        v = v * t + a.y;
        v = v * t + a.z;
        v = v * t + a.w;
        v = v * t + b.x;
        v = v * t + b.y;
        out[base + gid] = v;
    }
}

extern "C" void kernel_launch(void* const* d_in, const int* in_sizes, int n_in,
                              void* d_out, int out_size)
{
    const float* x     = (const float*)d_in[0];
    const float* knots = (const float*)d_in[1];
    const float* fv    = (const float*)d_in[2];
    float* out = (float*)d_out;

    int n  = in_sizes[0];
    int nk = in_sizes[1];

    cudaFuncSetAttribute(quintic_spline_kernel,
                         cudaFuncAttributePreferredSharedMemoryCarveout, 100);

    const int threads = 384;
    int n4 = (n + 3) >> 2;
    int blocks = (n4 + threads - 1) / threads;
    int cap = 148 * 4;  // 4 blocks/SM * 384 = 1536 threads/SM
    if (blocks > cap) blocks = cap;
    if (blocks < 1) blocks = 1;

    size_t smem_bytes = (size_t)2 * nk * sizeof(float4);
    quintic_spline_kernel<<<blocks, threads, smem_bytes>>>(x, knots, fv, out, n, nk);
}